// round 7
// baseline (speedup 1.0000x reference)
#include <cuda_runtime.h>

// Grouped mean over skeleton nodes:
//   in  : [32, 512, 21, 256] f32   (bt = 16384 rows of 21*256)
//   out : [32, 512, 10, 256] f32
// NODE_MAP = [[1,2],[3,4],[5,6],[7,8],[0,9],[10,11,12],[13,14],[15,16],[17,18],[19,20]]
//
// 256-bit (v8) variant: each thread produces one 32B output chunk.
// total8 = 32*512*10*32 = 1,310,720 v8 outputs; divisible by 256 -> no tail.

__constant__ int   c_n0[10]    = {1, 3, 5, 7, 0, 10, 13, 15, 17, 19};
__constant__ int   c_n1[10]    = {2, 4, 6, 8, 9, 11, 14, 16, 18, 20};
__constant__ int   c_n2[10]    = {-1, -1, -1, -1, -1, 12, -1, -1, -1, -1};
__constant__ float c_scale[10] = {0.5f, 0.5f, 0.5f, 0.5f, 0.5f,
                                  1.0f / 3.0f, 0.5f, 0.5f, 0.5f, 0.5f};

static constexpr int C8      = 32;        // 256 f32 / 8 per node row (32B units)
static constexpr int IN_ROW8 = 21 * C8;   // 672 v8 per bt row (input)

struct f8 { float v[8]; };

// 256-bit evict-first streaming load/store (sm_100+).
__device__ __forceinline__ f8 ld_cs8(const float* p) {
    f8 r;
    asm volatile("ld.global.cs.v8.f32 {%0,%1,%2,%3,%4,%5,%6,%7}, [%8];"
                 : "=f"(r.v[0]), "=f"(r.v[1]), "=f"(r.v[2]), "=f"(r.v[3]),
                   "=f"(r.v[4]), "=f"(r.v[5]), "=f"(r.v[6]), "=f"(r.v[7])
                 : "l"(p));
    return r;
}
__device__ __forceinline__ void st_cs8(float* p, const f8& r) {
    asm volatile("st.global.cs.v8.f32 [%0], {%1,%2,%3,%4,%5,%6,%7,%8};"
                 :: "l"(p),
                    "f"(r.v[0]), "f"(r.v[1]), "f"(r.v[2]), "f"(r.v[3]),
                    "f"(r.v[4]), "f"(r.v[5]), "f"(r.v[6]), "f"(r.v[7])
                 : "memory");
}

__global__ __launch_bounds__(256)
void s_down_sampling_kernel(const float* __restrict__ in,
                            float* __restrict__ out)
{
    int idx = blockIdx.x * blockDim.x + threadIdx.x;   // v8 output index

    int c8  = idx & (C8 - 1);
    int tmp = idx >> 5;              // bt*10 + m
    int m   = tmp % 10;
    int bt  = tmp / 10;

    const float* row = in + (long long)bt * (IN_ROW8 * 8);
    int coff = c8 * 8;

    f8 a = ld_cs8(row + c_n0[m] * 256 + coff);
    f8 b = ld_cs8(row + c_n1[m] * 256 + coff);

    float s = c_scale[m];
    f8 r;

    int n2 = c_n2[m];
    if (n2 >= 0) {
        f8 c = ld_cs8(row + n2 * 256 + coff);
        #pragma unroll
        for (int i = 0; i < 8; i++)
            r.v[i] = (a.v[i] + b.v[i] + c.v[i]) * s;
    } else {
        #pragma unroll
        for (int i = 0; i < 8; i++)
            r.v[i] = (a.v[i] + b.v[i]) * s;
    }

    st_cs8(out + (long long)idx * 8, r);
}

extern "C" void kernel_launch(void* const* d_in, const int* in_sizes, int n_in,
                              void* d_out, int out_size)
{
    const float* in  = (const float*)d_in[0];
    float*       out = (float*)d_out;

    int total8  = out_size / 8;      // 1,310,720
    int threads = 256;
    int blocks  = total8 / threads;  // 5120, exact cover
    s_down_sampling_kernel<<<blocks, threads>>>(in, out);
}